// round 3
// baseline (speedup 1.0000x reference)
#include <cuda_runtime.h>

// Problem constants (fixed shapes per the dataset)
#define NG    128      // graphs
#define NPG   64       // nodes per graph
#define NND   8192     // total nodes
#define EPG   1024     // edges per graph (NPG*DEG)
#define ETOT  131072   // total edges
#define HD    128      // hidden / input dim
#define FD    384      // 3*H concat feature dim
#define KSEL  32       // top-k per graph
#define DOUT  10
#define NT    256      // threads per CTA

// Shared memory layout (in floats)
#define OFF_A     0                      // 64*64          = 4096
#define OFF_XS    (OFF_A + 4096)         // 64*128         = 8192
#define OFF_TMP   (OFF_XS + 8192)        // 64*128         = 8192
#define OFF_FEATS (OFF_TMP + 8192)       // 64*384         = 24576
#define OFF_WC    (OFF_FEATS + 24576)    // 32*128 staging = 4096 (reused as psum scratch)
#define OFF_SCORE (OFF_WC + 4096)        // 64
#define OFF_TVEC  (OFF_SCORE + 64)       // 64 (dinv, then feats@Wa)
#define OFF_SEL   (OFF_TVEC + 64)        // 64 (int flags)
#define OFF_RD    (OFF_SEL + 64)         // 768 readout
#define OFF_T1    (OFF_RD + 768)         // 128
#define OFF_T2    (OFF_T1 + 128)         // 64
#define OFF_WAS   (OFF_T2 + 64)          // 384 Wa cache
#define SMEM_FLOATS (OFF_WAS + 384)      // = 50688 floats -> 202752 bytes

// tmp[64][128] = In[64][KD=128](smem, stride inStride) @ Wg[128][128](global, staged via Wc)
__device__ __forceinline__ void gemm_xw(const float* __restrict__ In, int inStride,
                                        const float* __restrict__ Wg,
                                        float* __restrict__ Wc, float* __restrict__ tmp,
                                        int tid, int tr, int tc)
{
    float4 acc[8];
#pragma unroll
    for (int r = 0; r < 8; ++r) acc[r] = make_float4(0.f, 0.f, 0.f, 0.f);

    for (int kc = 0; kc < 128; kc += 32) {
        __syncthreads();  // protect Wc reuse + order feats/tmp writes before reads
        const float4* src = (const float4*)(Wg + kc * 128);
        float4* dst = (float4*)Wc;
#pragma unroll
        for (int i = 0; i < 4; ++i) dst[tid + i * NT] = src[tid + i * NT];
        __syncthreads();
#pragma unroll 4
        for (int k = 0; k < 32; ++k) {
            float4 w = ((const float4*)Wc)[k * 32 + tc];
#pragma unroll
            for (int r = 0; r < 8; ++r) {
                float a = In[(tr + r * 8) * inStride + kc + k];  // warp-broadcast
                acc[r].x = fmaf(a, w.x, acc[r].x);
                acc[r].y = fmaf(a, w.y, acc[r].y);
                acc[r].z = fmaf(a, w.z, acc[r].z);
                acc[r].w = fmaf(a, w.w, acc[r].w);
            }
        }
    }
    __syncthreads();
#pragma unroll
    for (int r = 0; r < 8; ++r) ((float4*)tmp)[(tr + r * 8) * 32 + tc] = acc[r];
}

// featsDst[64][(stride FD)] = relu(A[64][64] @ tmp[64][128] + b)
__device__ __forceinline__ void amult_relu(const float* __restrict__ A,
                                           const float* __restrict__ tmp,
                                           const float* __restrict__ bvec,
                                           float* __restrict__ featsDst,
                                           int tr, int tc)
{
    float4 acc[8];
#pragma unroll
    for (int r = 0; r < 8; ++r) acc[r] = make_float4(0.f, 0.f, 0.f, 0.f);
    __syncthreads();  // tmp ready
#pragma unroll 4
    for (int k = 0; k < 64; ++k) {
        float4 t = ((const float4*)tmp)[k * 32 + tc];
#pragma unroll
        for (int r = 0; r < 8; ++r) {
            float a = A[(tr + r * 8) * 64 + k];  // warp-broadcast
            acc[r].x = fmaf(a, t.x, acc[r].x);
            acc[r].y = fmaf(a, t.y, acc[r].y);
            acc[r].z = fmaf(a, t.z, acc[r].z);
            acc[r].w = fmaf(a, t.w, acc[r].w);
        }
    }
    float4 bb = ((const float4*)bvec)[tc];
#pragma unroll
    for (int r = 0; r < 8; ++r) {
        float4 v;
        v.x = fmaxf(acc[r].x + bb.x, 0.f);
        v.y = fmaxf(acc[r].y + bb.y, 0.f);
        v.z = fmaxf(acc[r].z + bb.z, 0.f);
        v.w = fmaxf(acc[r].w + bb.w, 0.f);
        ((float4*)featsDst)[(tr + r * 8) * (FD / 4) + tc] = v;
    }
    __syncthreads();
}

__global__ void __launch_bounds__(NT, 1)
sagpool_kernel(const float* __restrict__ x, const int* __restrict__ ei,
               const float* __restrict__ W1, const float* __restrict__ b1,
               const float* __restrict__ W2, const float* __restrict__ b2,
               const float* __restrict__ W3, const float* __restrict__ b3,
               const float* __restrict__ Wa, const float* __restrict__ ba,
               const float* __restrict__ M1, const float* __restrict__ c1,
               const float* __restrict__ M2, const float* __restrict__ c2,
               const float* __restrict__ M3, const float* __restrict__ c3,
               float* __restrict__ out)
{
    extern __shared__ float sm[];
    float* A     = sm + OFF_A;
    float* xs    = sm + OFF_XS;
    float* tmp   = sm + OFF_TMP;
    float* feats = sm + OFF_FEATS;
    float* Wc    = sm + OFF_WC;
    float* score = sm + OFF_SCORE;
    float* tvec  = sm + OFF_TVEC;
    int*   sel   = (int*)(sm + OFF_SEL);
    float* rdout = sm + OFF_RD;
    float* t1    = sm + OFF_T1;
    float* t2    = sm + OFF_T2;
    float* was   = sm + OFF_WAS;

    const int g   = blockIdx.x;
    const int tid = threadIdx.x;
    const int tc  = tid & 31;
    const int tr  = tid >> 5;
    const int base = g * NPG;

    // ---- build binary adjacency (symmetrized) ----
    for (int i = tid; i < NPG * NPG; i += NT) A[i] = 0.f;
    __syncthreads();
    {
        const int* es = ei + g * EPG;
        const int* ed = ei + ETOT + g * EPG;
        for (int e = tid; e < EPG; e += NT) {
            int s = es[e] - base;
            int d = ed[e] - base;
            A[s * 64 + d] = 1.f;
            A[d * 64 + s] = 1.f;
        }
    }
    __syncthreads();
    // ---- A += I (diag can become 2 with self-loops), rowsum, dinv ----
    if (tid < 64) {
        A[tid * 64 + tid] += 1.f;
        float s = 0.f;
        for (int k = 0; k < 64; ++k) s += A[tid * 64 + k];
        tvec[tid] = rsqrtf(s);  // dinv
    }
    __syncthreads();
    for (int i = tid; i < NPG * NPG; i += NT)
        A[i] *= tvec[i >> 6] * tvec[i & 63];
    // load x tile + Wa cache (reads ordered by gemm's internal syncs)
    for (int i = tid; i < NPG * HD; i += NT) xs[i] = x[base * HD + i];
    for (int i = tid; i < FD; i += NT) was[i] = Wa[i];

    // ---- 3 GCN layers: h = relu(A @ (In @ W) + b) ----
    gemm_xw(xs, HD, W1, Wc, tmp, tid, tr, tc);
    amult_relu(A, tmp, b1, feats + 0, tr, tc);
    gemm_xw(feats + 0, FD, W2, Wc, tmp, tid, tr, tc);
    amult_relu(A, tmp, b2, feats + 128, tr, tc);
    gemm_xw(feats + 128, FD, W3, Wc, tmp, tid, tr, tc);
    amult_relu(A, tmp, b3, feats + 256, tr, tc);

    // ---- attention: score = tanh(A @ (feats @ Wa) + ba) ----
    {
        int row = tid >> 2, l4 = tid & 3;
        float part = 0.f;
        for (int c = l4; c < FD; c += 4) part = fmaf(feats[row * FD + c], was[c], part);
        part += __shfl_xor_sync(0xFFFFFFFFu, part, 1);
        part += __shfl_xor_sync(0xFFFFFFFFu, part, 2);
        if (l4 == 0) tvec[row] = part;
    }
    __syncthreads();
    if (tid < 64) {
        float s = 0.f;
        for (int k = 0; k < 64; ++k) s = fmaf(A[tid * 64 + k], tvec[k], s);
        score[tid] = tanhf(s + ba[0]);
    }
    __syncthreads();
    // ---- top-K (jax top_k tie-break: smaller index wins among equals) ----
    if (tid < 64) {
        float si = score[tid];
        int rank = 0;
        for (int j = 0; j < 64; ++j) {
            float sj = score[j];
            rank += (sj > si) || (sj == si && j < tid);
        }
        sel[tid] = (rank < KSEL) ? 1 : 0;
    }
    __syncthreads();
    // ---- readout: mean || max of feats*score over selected ----
    for (int c = tid; c < FD; c += NT) {
        float ssum = 0.f, mx = -3.402823466e+38f;
        for (int i = 0; i < 64; ++i) {
            if (sel[i]) {
                float v = feats[i * FD + c] * score[i];
                ssum += v;
                mx = fmaxf(mx, v);
            }
        }
        rdout[c]      = ssum * (1.f / (float)KSEL);
        rdout[FD + c] = mx;
    }
    __syncthreads();
    // ---- MLP layer 1: [768] -> [128], split the dot across 2 threads ----
    {
        float* psum = Wc;  // scratch (free now)
        int j = tid & 127, half = tid >> 7;
        float a = 0.f;
        int c0 = half * (FD * 2 / 2);  // 0 or 384
        for (int c = c0; c < c0 + FD; ++c)
            a = fmaf(rdout[c], M1[c * HD + j], a);
        psum[tid] = a;
        __syncthreads();
        if (tid < 128) t1[tid] = fmaxf(psum[tid] + psum[tid + 128] + c1[tid], 0.f);
    }
    __syncthreads();
    // ---- MLP layer 2: [128] -> [64], split 4 ways ----
    {
        float* psum = Wc;
        int j = tid & 63, part = tid >> 6;
        float a = 0.f;
        for (int c = part * 32; c < part * 32 + 32; ++c)
            a = fmaf(t1[c], M2[c * 64 + j], a);
        psum[tid] = a;
        __syncthreads();
        if (tid < 64)
            t2[tid] = fmaxf(psum[tid] + psum[tid + 64] + psum[tid + 128] + psum[tid + 192] + c2[tid], 0.f);
    }
    __syncthreads();
    // ---- MLP layer 3: [64] -> [10] ----
    if (tid < DOUT) {
        float a = c3[tid];
        for (int c = 0; c < 64; ++c) a = fmaf(t2[c], M3[c * DOUT + tid], a);
        out[g * DOUT + tid] = a;
    }
}

extern "C" void kernel_launch(void* const* d_in, const int* in_sizes, int n_in,
                              void* d_out, int out_size)
{
    const float* x  = (const float*)d_in[0];
    const int*   ei = (const int*)d_in[1];
    // d_in[2] = batch (unused: graphs are contiguous 64-node blocks)
    const float* W1 = (const float*)d_in[3];
    const float* b1 = (const float*)d_in[4];
    const float* W2 = (const float*)d_in[5];
    const float* b2 = (const float*)d_in[6];
    const float* W3 = (const float*)d_in[7];
    const float* b3 = (const float*)d_in[8];
    const float* Wa = (const float*)d_in[9];
    const float* ba = (const float*)d_in[10];
    const float* M1 = (const float*)d_in[11];
    const float* c1 = (const float*)d_in[12];
    const float* M2 = (const float*)d_in[13];
    const float* c2 = (const float*)d_in[14];
    const float* M3 = (const float*)d_in[15];
    const float* c3 = (const float*)d_in[16];
    float* out = (float*)d_out;

    const int smem_bytes = SMEM_FLOATS * (int)sizeof(float);
    cudaFuncSetAttribute(sagpool_kernel,
                         cudaFuncAttributeMaxDynamicSharedMemorySize, smem_bytes);
    sagpool_kernel<<<NG, NT, smem_bytes>>>(x, ei, W1, b1, W2, b2, W3, b3,
                                           Wa, ba, M1, c1, M2, c2, M3, c3, out);
}

// round 5
// speedup vs baseline: 1.1564x; 1.1564x over previous
#include <cuda_runtime.h>
#include <float.h>

// Problem constants (fixed shapes per the dataset)
#define NG    128      // graphs
#define NPG   64       // nodes per graph
#define EPG   1024     // edges per graph (NPG*DEG)
#define ETOT  131072   // total edges
#define HD    128      // hidden / input dim
#define FD    384      // 3*H concat feature dim
#define KSEL  32       // top-k per graph
#define DOUT  10
#define NT    512      // threads per CTA (16 warps)

// Shared memory layout (float indices)
#define OFF_A     0                      // 64*64   = 4096
#define OFF_XS    4096                   // 64*128  = 8192
#define OFF_TMP   12288                  // 64*128  = 8192
#define OFF_FEATS 20480                  // 64*384  = 24576
#define OFF_WC    45056                  // 64*128  = 8192 staging (reused as psum[512])
#define OFF_SCORE 53248                  // 64
#define OFF_TVEC  53312                  // 64
#define OFF_SLIST 53376                  // 32 (int) selected indices
#define OFF_SCNT  53408                  // 1  (int) counter (+pad)
#define OFF_RD    53440                  // 768 readout
#define OFF_T1    54208                  // 128
#define OFF_T2    54336                  // 64
#define OFF_WAS   54400                  // 384 Wa cache
#define SMEM_FLOATS 54784                // 219136 bytes

// inline function — no macro token-substitution hazards
__device__ __forceinline__ void fma4(float4& acc, float s, const float4& v)
{
    acc.x = fmaf(s, v.x, acc.x);
    acc.y = fmaf(s, v.y, acc.y);
    acc.z = fmaf(s, v.z, acc.z);
    acc.w = fmaf(s, v.w, acc.w);
}

// tmp[64][128] = In[64][128](smem, row stride inStride) @ Wg[128][128](global, staged)
// thread tile: rows 4*tr..4*tr+3, cols 4*tc..4*tc+3
__device__ __forceinline__ void gemm_xw(const float* __restrict__ In, int inStride,
                                        const float* __restrict__ Wg,
                                        float* __restrict__ Wc, float* __restrict__ tmp,
                                        int tid, int tr, int tc)
{
    float4 acc[4];
#pragma unroll
    for (int r = 0; r < 4; ++r) acc[r] = make_float4(0.f, 0.f, 0.f, 0.f);

    const float4* Wc4 = (const float4*)Wc;
    for (int kc = 0; kc < 128; kc += 64) {
        __syncthreads();  // protect Wc reuse; also orders In(feats) writes before reads
        {   // stage 64x128 chunk of W
            const float4* src = (const float4*)(Wg + kc * HD);
            float4* dst = (float4*)Wc;
#pragma unroll
            for (int i = 0; i < 4; ++i) dst[tid + i * NT] = src[tid + i * NT];
        }
        __syncthreads();
#pragma unroll 4
        for (int k = 0; k < 64; k += 4) {
            // operand A: float4 along k, warp-broadcast (all lanes share tr)
            float4 a0 = *(const float4*)(In + (4 * tr + 0) * inStride + kc + k);
            float4 a1 = *(const float4*)(In + (4 * tr + 1) * inStride + kc + k);
            float4 a2 = *(const float4*)(In + (4 * tr + 2) * inStride + kc + k);
            float4 a3 = *(const float4*)(In + (4 * tr + 3) * inStride + kc + k);
            float4 w0 = Wc4[(k + 0) * 32 + tc];
            float4 w1 = Wc4[(k + 1) * 32 + tc];
            float4 w2 = Wc4[(k + 2) * 32 + tc];
            float4 w3 = Wc4[(k + 3) * 32 + tc];
            fma4(acc[0], a0.x, w0); fma4(acc[0], a0.y, w1); fma4(acc[0], a0.z, w2); fma4(acc[0], a0.w, w3);
            fma4(acc[1], a1.x, w0); fma4(acc[1], a1.y, w1); fma4(acc[1], a1.z, w2); fma4(acc[1], a1.w, w3);
            fma4(acc[2], a2.x, w0); fma4(acc[2], a2.y, w1); fma4(acc[2], a2.z, w2); fma4(acc[2], a2.w, w3);
            fma4(acc[3], a3.x, w0); fma4(acc[3], a3.y, w1); fma4(acc[3], a3.z, w2); fma4(acc[3], a3.w, w3);
        }
    }
    __syncthreads();
#pragma unroll
    for (int r = 0; r < 4; ++r)
        ((float4*)tmp)[(4 * tr + r) * 32 + tc] = acc[r];
}

// featsDst[64][stride FD] = relu(A[64][64] @ tmp[64][128] + b)
__device__ __forceinline__ void amult_relu(const float* __restrict__ A,
                                           const float* __restrict__ tmp,
                                           const float* __restrict__ bvec,
                                           float* __restrict__ featsDst,
                                           int tr, int tc)
{
    float4 acc[4];
#pragma unroll
    for (int r = 0; r < 4; ++r) acc[r] = make_float4(0.f, 0.f, 0.f, 0.f);
    __syncthreads();  // tmp ready
    const float4* T4 = (const float4*)tmp;
#pragma unroll 4
    for (int k = 0; k < 64; k += 4) {
        float4 a0 = *(const float4*)(A + (4 * tr + 0) * 64 + k);  // broadcast
        float4 a1 = *(const float4*)(A + (4 * tr + 1) * 64 + k);
        float4 a2 = *(const float4*)(A + (4 * tr + 2) * 64 + k);
        float4 a3 = *(const float4*)(A + (4 * tr + 3) * 64 + k);
        float4 t0 = T4[(k + 0) * 32 + tc];
        float4 t1 = T4[(k + 1) * 32 + tc];
        float4 t2 = T4[(k + 2) * 32 + tc];
        float4 t3 = T4[(k + 3) * 32 + tc];
        fma4(acc[0], a0.x, t0); fma4(acc[0], a0.y, t1); fma4(acc[0], a0.z, t2); fma4(acc[0], a0.w, t3);
        fma4(acc[1], a1.x, t0); fma4(acc[1], a1.y, t1); fma4(acc[1], a1.z, t2); fma4(acc[1], a1.w, t3);
        fma4(acc[2], a2.x, t0); fma4(acc[2], a2.y, t1); fma4(acc[2], a2.z, t2); fma4(acc[2], a2.w, t3);
        fma4(acc[3], a3.x, t0); fma4(acc[3], a3.y, t1); fma4(acc[3], a3.z, t2); fma4(acc[3], a3.w, t3);
    }
    float4 bb = ((const float4*)bvec)[tc];
#pragma unroll
    for (int r = 0; r < 4; ++r) {
        float4 v;
        v.x = fmaxf(acc[r].x + bb.x, 0.f);
        v.y = fmaxf(acc[r].y + bb.y, 0.f);
        v.z = fmaxf(acc[r].z + bb.z, 0.f);
        v.w = fmaxf(acc[r].w + bb.w, 0.f);
        ((float4*)featsDst)[(4 * tr + r) * (FD / 4) + tc] = v;
    }
    __syncthreads();
}

__global__ void __launch_bounds__(NT, 1)
sagpool_kernel(const float* __restrict__ x, const int* __restrict__ ei,
               const float* __restrict__ W1, const float* __restrict__ b1,
               const float* __restrict__ W2, const float* __restrict__ b2,
               const float* __restrict__ W3, const float* __restrict__ b3,
               const float* __restrict__ Wa, const float* __restrict__ ba,
               const float* __restrict__ M1, const float* __restrict__ c1,
               const float* __restrict__ M2, const float* __restrict__ c2,
               const float* __restrict__ M3, const float* __restrict__ c3,
               float* __restrict__ out)
{
    extern __shared__ float sm[];
    float* A     = sm + OFF_A;
    float* xs    = sm + OFF_XS;
    float* tmp   = sm + OFF_TMP;
    float* feats = sm + OFF_FEATS;
    float* Wc    = sm + OFF_WC;
    float* score = sm + OFF_SCORE;
    float* tvec  = sm + OFF_TVEC;
    int*   slist = (int*)(sm + OFF_SLIST);
    int*   scnt  = (int*)(sm + OFF_SCNT);
    float* rdout = sm + OFF_RD;
    float* t1    = sm + OFF_T1;
    float* t2    = sm + OFF_T2;
    float* was   = sm + OFF_WAS;

    const int g   = blockIdx.x;
    const int tid = threadIdx.x;
    const int tc  = tid & 31;
    const int tr  = tid >> 5;   // 0..15
    const int base = g * NPG;
    const int row8 = tid >> 3;  // 0..63  (8 threads per row)
    const int l8   = tid & 7;

    // ---- build binary adjacency (symmetrized) ----
    for (int i = tid; i < NPG * NPG; i += NT) A[i] = 0.f;
    if (tid == 0) *scnt = 0;
    __syncthreads();
    {
        const int* es = ei + g * EPG;
        const int* ed = ei + ETOT + g * EPG;
#pragma unroll
        for (int e = tid; e < EPG; e += NT) {
            int s = es[e] - base;
            int d = ed[e] - base;
            A[s * 64 + d] = 1.f;
            A[d * 64 + s] = 1.f;
        }
    }
    __syncthreads();
    if (tid < 64) A[tid * 64 + tid] += 1.f;   // A += I (diag may reach 2)
    __syncthreads();
    {   // rowsum -> dinv, 8 threads per row
        float s = 0.f;
#pragma unroll
        for (int k = l8; k < 64; k += 8) s += A[row8 * 64 + k];
        s += __shfl_xor_sync(0xFFFFFFFFu, s, 1);
        s += __shfl_xor_sync(0xFFFFFFFFu, s, 2);
        s += __shfl_xor_sync(0xFFFFFFFFu, s, 4);
        if (l8 == 0) tvec[row8] = rsqrtf(s);
    }
    __syncthreads();
    for (int i = tid; i < NPG * NPG; i += NT)
        A[i] *= tvec[i >> 6] * tvec[i & 63];
    // load x tile (float4) + Wa cache — reads ordered by gemm's internal syncs
    {
        const float4* xg = (const float4*)(x + base * HD);
        float4* xd = (float4*)xs;
#pragma unroll
        for (int i = 0; i < 4; ++i) xd[tid + i * NT] = xg[tid + i * NT];
    }
    if (tid < FD) was[tid] = Wa[tid];

    // ---- 3 GCN layers: h = relu(A @ (In @ W) + b) ----
    gemm_xw(xs, HD, W1, Wc, tmp, tid, tr, tc);
    amult_relu(A, tmp, b1, feats + 0, tr, tc);
    gemm_xw(feats + 0, FD, W2, Wc, tmp, tid, tr, tc);
    amult_relu(A, tmp, b2, feats + 128, tr, tc);
    gemm_xw(feats + 128, FD, W3, Wc, tmp, tid, tr, tc);
    amult_relu(A, tmp, b3, feats + 256, tr, tc);

    // ---- attention: score = tanh(A @ (feats @ Wa) + ba) ----
    {
        float p = 0.f;
#pragma unroll
        for (int c = l8; c < FD; c += 8) p = fmaf(feats[row8 * FD + c], was[c], p);
        p += __shfl_xor_sync(0xFFFFFFFFu, p, 1);
        p += __shfl_xor_sync(0xFFFFFFFFu, p, 2);
        p += __shfl_xor_sync(0xFFFFFFFFu, p, 4);
        if (l8 == 0) tvec[row8] = p;
    }
    __syncthreads();
    {
        float s = 0.f;
#pragma unroll
        for (int k = l8; k < 64; k += 8) s = fmaf(A[row8 * 64 + k], tvec[k], s);
        s += __shfl_xor_sync(0xFFFFFFFFu, s, 1);
        s += __shfl_xor_sync(0xFFFFFFFFu, s, 2);
        s += __shfl_xor_sync(0xFFFFFFFFu, s, 4);
        if (l8 == 0) score[row8] = tanhf(s + ba[0]);
    }
    __syncthreads();
    // ---- top-K (jax top_k tie-break: smaller index wins among equals) ----
    if (tid < 64) {
        float si = score[tid];
        int rank = 0;
#pragma unroll
        for (int j = 0; j < 64; ++j) {
            float sj = score[j];
            rank += (sj > si) || (sj == si && j < tid);
        }
        if (rank < KSEL) {
            int p = atomicAdd(scnt, 1);
            slist[p] = tid;      // unordered OK: mean & max are order-invariant
        }
    }
    __syncthreads();
    // ---- readout: mean || max of feats*score over selected ----
    if (tid < FD) {
        float ssum = 0.f, mx = -FLT_MAX;
#pragma unroll
        for (int j = 0; j < KSEL; ++j) {
            int i = slist[j];
            float v = feats[i * FD + tid] * score[i];
            ssum += v;
            mx = fmaxf(mx, v);
        }
        rdout[tid]      = ssum * (1.f / (float)KSEL);
        rdout[FD + tid] = mx;
    }
    __syncthreads();
    // ---- MLP layer 1: [768] -> [128], 4 partial sums per output ----
    {
        float* psum = Wc;  // scratch
        int j = tid & 127, q = tid >> 7;  // q: 0..3
        float a = 0.f;
        for (int c = q * 192; c < q * 192 + 192; ++c)
            a = fmaf(rdout[c], M1[c * HD + j], a);
        psum[tid] = a;
        __syncthreads();
        if (tid < 128)
            t1[tid] = fmaxf(psum[tid] + psum[tid + 128] + psum[tid + 256] + psum[tid + 384] + c1[tid], 0.f);
    }
    __syncthreads();
    // ---- MLP layer 2: [128] -> [64], 8 partial sums per output ----
    {
        float* psum = Wc;
        int j = tid & 63, q = tid >> 6;  // q: 0..7
        float a = 0.f;
#pragma unroll
        for (int c = q * 16; c < q * 16 + 16; ++c)
            a = fmaf(t1[c], M2[c * 64 + j], a);
        psum[tid] = a;
        __syncthreads();
        if (tid < 64) {
            float s = c2[tid];
#pragma unroll
            for (int q2 = 0; q2 < 8; ++q2) s += psum[tid + q2 * 64];
            t2[tid] = fmaxf(s, 0.f);
        }
    }
    __syncthreads();
    // ---- MLP layer 3: [64] -> [10] ----
    if (tid < DOUT) {
        float a = c3[tid];
#pragma unroll
        for (int c = 0; c < 64; ++c) a = fmaf(t2[c], M3[c * DOUT + tid], a);
        out[g * DOUT + tid] = a;
    }
}

extern "C" void kernel_launch(void* const* d_in, const int* in_sizes, int n_in,
                              void* d_out, int out_size)
{
    const float* x  = (const float*)d_in[0];
    const int*   ei = (const int*)d_in[1];
    // d_in[2] = batch (unused: graphs are contiguous 64-node blocks)
    const float* W1 = (const float*)d_in[3];
    const float* b1 = (const float*)d_in[4];
    const float* W2 = (const float*)d_in[5];
    const float* b2 = (const float*)d_in[6];
    const float* W3 = (const float*)d_in[7];
    const float* b3 = (const float*)d_in[8];
    const float* Wa = (const float*)d_in[9];
    const float* ba = (const float*)d_in[10];
    const float* M1 = (const float*)d_in[11];
    const float* c1 = (const float*)d_in[12];
    const float* M2 = (const float*)d_in[13];
    const float* c2 = (const float*)d_in[14];
    const float* M3 = (const float*)d_in[15];
    const float* c3 = (const float*)d_in[16];
    float* out = (float*)d_out;

    const int smem_bytes = SMEM_FLOATS * (int)sizeof(float);
    cudaFuncSetAttribute(sagpool_kernel,
                         cudaFuncAttributeMaxDynamicSharedMemorySize, smem_bytes);
    sagpool_kernel<<<NG, NT, smem_bytes>>>(x, ei, W1, b1, W2, b2, W3, b3,
                                           Wa, ba, M1, c1, M2, c2, M3, c3, out);
}

// round 6
// speedup vs baseline: 1.1626x; 1.0054x over previous
#include <cuda_runtime.h>
#include <float.h>

// Problem constants (fixed shapes per the dataset)
#define NG    128      // graphs
#define NPG   64       // nodes per graph
#define EPG   1024     // edges per graph (NPG*DEG)
#define ETOT  131072   // total edges
#define HD    128      // hidden / input dim
#define FD    384      // 3*H concat feature dim
#define KSEL  32       // top-k per graph
#define DOUT  10
#define NT    512      // threads per CTA (16 warps)

// Shared memory layout (float indices)
#define OFF_A     0                      // 64*64   = 4096
#define OFF_XS    4096                   // 64*128  = 8192
#define OFF_TMP   12288                  // 64*128  = 8192
#define OFF_FEATS 20480                  // 64*384  = 24576
#define OFF_WC    45056                  // 64*128  = 8192 staging (reused as psum[512])
#define OFF_SCORE 53248                  // 64
#define OFF_TVEC  53312                  // 64
#define OFF_SLIST 53376                  // 32 (int) selected indices
#define OFF_SCNT  53408                  // 1  (int) counter (+pad)
#define OFF_RD    53440                  // 768 readout
#define OFF_T1    54208                  // 128
#define OFF_T2    54336                  // 64
#define OFF_WAS   54400                  // 384 Wa cache
#define SMEM_FLOATS 54784                // 219136 bytes

// inline function — no macro token-substitution hazards
__device__ __forceinline__ void fma4(float4& acc, float s, const float4& v)
{
    acc.x = fmaf(s, v.x, acc.x);
    acc.y = fmaf(s, v.y, acc.y);
    acc.z = fmaf(s, v.z, acc.z);
    acc.w = fmaf(s, v.w, acc.w);
}

// tmp[64][128] = In[64][128](smem, row stride inStride) @ Wg[128][128](global, staged)
// thread tile: rows 4*tr..4*tr+3, cols 4*tc..4*tc+3
__device__ __forceinline__ void gemm_xw(const float* __restrict__ In, int inStride,
                                        const float* __restrict__ Wg,
                                        float* __restrict__ Wc, float* __restrict__ tmp,
                                        int tid, int tr, int tc)
{
    float4 acc[4];
#pragma unroll
    for (int r = 0; r < 4; ++r) acc[r] = make_float4(0.f, 0.f, 0.f, 0.f);

    const float4* Wc4 = (const float4*)Wc;
    for (int kc = 0; kc < 128; kc += 64) {
        __syncthreads();  // protect Wc reuse; also orders In(feats) writes before reads
        {   // stage 64x128 chunk of W
            const float4* src = (const float4*)(Wg + kc * HD);
            float4* dst = (float4*)Wc;
#pragma unroll
            for (int i = 0; i < 4; ++i) dst[tid + i * NT] = src[tid + i * NT];
        }
        __syncthreads();
#pragma unroll 4
        for (int k = 0; k < 64; k += 4) {
            // operand A: float4 along k, warp-broadcast (all lanes share tr)
            float4 a0 = *(const float4*)(In + (4 * tr + 0) * inStride + kc + k);
            float4 a1 = *(const float4*)(In + (4 * tr + 1) * inStride + kc + k);
            float4 a2 = *(const float4*)(In + (4 * tr + 2) * inStride + kc + k);
            float4 a3 = *(const float4*)(In + (4 * tr + 3) * inStride + kc + k);
            float4 w0 = Wc4[(k + 0) * 32 + tc];
            float4 w1 = Wc4[(k + 1) * 32 + tc];
            float4 w2 = Wc4[(k + 2) * 32 + tc];
            float4 w3 = Wc4[(k + 3) * 32 + tc];
            fma4(acc[0], a0.x, w0); fma4(acc[0], a0.y, w1); fma4(acc[0], a0.z, w2); fma4(acc[0], a0.w, w3);
            fma4(acc[1], a1.x, w0); fma4(acc[1], a1.y, w1); fma4(acc[1], a1.z, w2); fma4(acc[1], a1.w, w3);
            fma4(acc[2], a2.x, w0); fma4(acc[2], a2.y, w1); fma4(acc[2], a2.z, w2); fma4(acc[2], a2.w, w3);
            fma4(acc[3], a3.x, w0); fma4(acc[3], a3.y, w1); fma4(acc[3], a3.z, w2); fma4(acc[3], a3.w, w3);
        }
    }
    __syncthreads();
#pragma unroll
    for (int r = 0; r < 4; ++r)
        ((float4*)tmp)[(4 * tr + r) * 32 + tc] = acc[r];
}

// featsDst[64][stride FD] = relu(A[64][64] @ tmp[64][128] + b)
__device__ __forceinline__ void amult_relu(const float* __restrict__ A,
                                           const float* __restrict__ tmp,
                                           const float* __restrict__ bvec,
                                           float* __restrict__ featsDst,
                                           int tr, int tc)
{
    float4 acc[4];
#pragma unroll
    for (int r = 0; r < 4; ++r) acc[r] = make_float4(0.f, 0.f, 0.f, 0.f);
    __syncthreads();  // tmp ready
    const float4* T4 = (const float4*)tmp;
#pragma unroll 4
    for (int k = 0; k < 64; k += 4) {
        float4 a0 = *(const float4*)(A + (4 * tr + 0) * 64 + k);  // broadcast
        float4 a1 = *(const float4*)(A + (4 * tr + 1) * 64 + k);
        float4 a2 = *(const float4*)(A + (4 * tr + 2) * 64 + k);
        float4 a3 = *(const float4*)(A + (4 * tr + 3) * 64 + k);
        float4 t0 = T4[(k + 0) * 32 + tc];
        float4 t1 = T4[(k + 1) * 32 + tc];
        float4 t2 = T4[(k + 2) * 32 + tc];
        float4 t3 = T4[(k + 3) * 32 + tc];
        fma4(acc[0], a0.x, t0); fma4(acc[0], a0.y, t1); fma4(acc[0], a0.z, t2); fma4(acc[0], a0.w, t3);
        fma4(acc[1], a1.x, t0); fma4(acc[1], a1.y, t1); fma4(acc[1], a1.z, t2); fma4(acc[1], a1.w, t3);
        fma4(acc[2], a2.x, t0); fma4(acc[2], a2.y, t1); fma4(acc[2], a2.z, t2); fma4(acc[2], a2.w, t3);
        fma4(acc[3], a3.x, t0); fma4(acc[3], a3.y, t1); fma4(acc[3], a3.z, t2); fma4(acc[3], a3.w, t3);
    }
    float4 bb = ((const float4*)bvec)[tc];
#pragma unroll
    for (int r = 0; r < 4; ++r) {
        float4 v;
        v.x = fmaxf(acc[r].x + bb.x, 0.f);
        v.y = fmaxf(acc[r].y + bb.y, 0.f);
        v.z = fmaxf(acc[r].z + bb.z, 0.f);
        v.w = fmaxf(acc[r].w + bb.w, 0.f);
        ((float4*)featsDst)[(4 * tr + r) * (FD / 4) + tc] = v;
    }
    __syncthreads();
}

__global__ void __launch_bounds__(NT, 1)
sagpool_kernel(const float* __restrict__ x, const int* __restrict__ ei,
               const float* __restrict__ W1, const float* __restrict__ b1,
               const float* __restrict__ W2, const float* __restrict__ b2,
               const float* __restrict__ W3, const float* __restrict__ b3,
               const float* __restrict__ Wa, const float* __restrict__ ba,
               const float* __restrict__ M1, const float* __restrict__ c1,
               const float* __restrict__ M2, const float* __restrict__ c2,
               const float* __restrict__ M3, const float* __restrict__ c3,
               float* __restrict__ out)
{
    extern __shared__ float sm[];
    float* A     = sm + OFF_A;
    float* xs    = sm + OFF_XS;
    float* tmp   = sm + OFF_TMP;
    float* feats = sm + OFF_FEATS;
    float* Wc    = sm + OFF_WC;
    float* score = sm + OFF_SCORE;
    float* tvec  = sm + OFF_TVEC;
    int*   slist = (int*)(sm + OFF_SLIST);
    int*   scnt  = (int*)(sm + OFF_SCNT);
    float* rdout = sm + OFF_RD;
    float* t1    = sm + OFF_T1;
    float* t2    = sm + OFF_T2;
    float* was   = sm + OFF_WAS;

    const int g   = blockIdx.x;
    const int tid = threadIdx.x;
    const int tc  = tid & 31;
    const int tr  = tid >> 5;   // 0..15
    const int base = g * NPG;
    const int row8 = tid >> 3;  // 0..63  (8 threads per row)
    const int l8   = tid & 7;

    // ---- build binary adjacency (symmetrized) ----
    for (int i = tid; i < NPG * NPG; i += NT) A[i] = 0.f;
    if (tid == 0) *scnt = 0;
    __syncthreads();
    {
        const int* es = ei + g * EPG;
        const int* ed = ei + ETOT + g * EPG;
#pragma unroll
        for (int e = tid; e < EPG; e += NT) {
            int s = es[e] - base;
            int d = ed[e] - base;
            A[s * 64 + d] = 1.f;
            A[d * 64 + s] = 1.f;
        }
    }
    __syncthreads();
    if (tid < 64) A[tid * 64 + tid] += 1.f;   // A += I (diag may reach 2)
    __syncthreads();
    {   // rowsum -> dinv, 8 threads per row
        float s = 0.f;
#pragma unroll
        for (int k = l8; k < 64; k += 8) s += A[row8 * 64 + k];
        s += __shfl_xor_sync(0xFFFFFFFFu, s, 1);
        s += __shfl_xor_sync(0xFFFFFFFFu, s, 2);
        s += __shfl_xor_sync(0xFFFFFFFFu, s, 4);
        if (l8 == 0) tvec[row8] = rsqrtf(s);
    }
    __syncthreads();
    for (int i = tid; i < NPG * NPG; i += NT)
        A[i] *= tvec[i >> 6] * tvec[i & 63];
    // load x tile (float4) + Wa cache — reads ordered by gemm's internal syncs
    {
        const float4* xg = (const float4*)(x + base * HD);
        float4* xd = (float4*)xs;
#pragma unroll
        for (int i = 0; i < 4; ++i) xd[tid + i * NT] = xg[tid + i * NT];
    }
    if (tid < FD) was[tid] = Wa[tid];

    // ---- 3 GCN layers: h = relu(A @ (In @ W) + b) ----
    gemm_xw(xs, HD, W1, Wc, tmp, tid, tr, tc);
    amult_relu(A, tmp, b1, feats + 0, tr, tc);
    gemm_xw(feats + 0, FD, W2, Wc, tmp, tid, tr, tc);
    amult_relu(A, tmp, b2, feats + 128, tr, tc);
    gemm_xw(feats + 128, FD, W3, Wc, tmp, tid, tr, tc);
    amult_relu(A, tmp, b3, feats + 256, tr, tc);

    // ---- attention: score = tanh(A @ (feats @ Wa) + ba) ----
    {
        float p = 0.f;
#pragma unroll
        for (int c = l8; c < FD; c += 8) p = fmaf(feats[row8 * FD + c], was[c], p);
        p += __shfl_xor_sync(0xFFFFFFFFu, p, 1);
        p += __shfl_xor_sync(0xFFFFFFFFu, p, 2);
        p += __shfl_xor_sync(0xFFFFFFFFu, p, 4);
        if (l8 == 0) tvec[row8] = p;
    }
    __syncthreads();
    {
        float s = 0.f;
#pragma unroll
        for (int k = l8; k < 64; k += 8) s = fmaf(A[row8 * 64 + k], tvec[k], s);
        s += __shfl_xor_sync(0xFFFFFFFFu, s, 1);
        s += __shfl_xor_sync(0xFFFFFFFFu, s, 2);
        s += __shfl_xor_sync(0xFFFFFFFFu, s, 4);
        if (l8 == 0) score[row8] = tanhf(s + ba[0]);
    }
    __syncthreads();
    // ---- top-K (jax top_k tie-break: smaller index wins among equals) ----
    if (tid < 64) {
        float si = score[tid];
        int rank = 0;
#pragma unroll
        for (int j = 0; j < 64; ++j) {
            float sj = score[j];
            rank += (sj > si) || (sj == si && j < tid);
        }
        if (rank < KSEL) {
            int p = atomicAdd(scnt, 1);
            slist[p] = tid;      // unordered OK: mean & max are order-invariant
        }
    }
    __syncthreads();
    // ---- readout: mean || max of feats*score over selected ----
    if (tid < FD) {
        float ssum = 0.f, mx = -FLT_MAX;
#pragma unroll
        for (int j = 0; j < KSEL; ++j) {
            int i = slist[j];
            float v = feats[i * FD + tid] * score[i];
            ssum += v;
            mx = fmaxf(mx, v);
        }
        rdout[tid]      = ssum * (1.f / (float)KSEL);
        rdout[FD + tid] = mx;
    }
    __syncthreads();
    // ---- MLP layer 1: [768] -> [128], 4 partial sums per output ----
    {
        float* psum = Wc;  // scratch
        int j = tid & 127, q = tid >> 7;  // q: 0..3
        float a = 0.f;
        for (int c = q * 192; c < q * 192 + 192; ++c)
            a = fmaf(rdout[c], M1[c * HD + j], a);
        psum[tid] = a;
        __syncthreads();
        if (tid < 128)
            t1[tid] = fmaxf(psum[tid] + psum[tid + 128] + psum[tid + 256] + psum[tid + 384] + c1[tid], 0.f);
    }
    __syncthreads();
    // ---- MLP layer 2: [128] -> [64], 8 partial sums per output ----
    {
        float* psum = Wc;
        int j = tid & 63, q = tid >> 6;  // q: 0..7
        float a = 0.f;
#pragma unroll
        for (int c = q * 16; c < q * 16 + 16; ++c)
            a = fmaf(t1[c], M2[c * 64 + j], a);
        psum[tid] = a;
        __syncthreads();
        if (tid < 64) {
            float s = c2[tid];
#pragma unroll
            for (int q2 = 0; q2 < 8; ++q2) s += psum[tid + q2 * 64];
            t2[tid] = fmaxf(s, 0.f);
        }
    }
    __syncthreads();
    // ---- MLP layer 3: [64] -> [10] ----
    if (tid < DOUT) {
        float a = c3[tid];
#pragma unroll
        for (int c = 0; c < 64; ++c) a = fmaf(t2[c], M3[c * DOUT + tid], a);
        out[g * DOUT + tid] = a;
    }
}

extern "C" void kernel_launch(void* const* d_in, const int* in_sizes, int n_in,
                              void* d_out, int out_size)
{
    const float* x  = (const float*)d_in[0];
    const int*   ei = (const int*)d_in[1];
    // d_in[2] = batch (unused: graphs are contiguous 64-node blocks)
    const float* W1 = (const float*)d_in[3];
    const float* b1 = (const float*)d_in[4];
    const float* W2 = (const float*)d_in[5];
    const float* b2 = (const float*)d_in[6];
    const float* W3 = (const float*)d_in[7];
    const float* b3 = (const float*)d_in[8];
    const float* Wa = (const float*)d_in[9];
    const float* ba = (const float*)d_in[10];
    const float* M1 = (const float*)d_in[11];
    const float* c1 = (const float*)d_in[12];
    const float* M2 = (const float*)d_in[13];
    const float* c2 = (const float*)d_in[14];
    const float* M3 = (const float*)d_in[15];
    const float* c3 = (const float*)d_in[16];
    float* out = (float*)d_out;

    const int smem_bytes = SMEM_FLOATS * (int)sizeof(float);
    cudaFuncSetAttribute(sagpool_kernel,
                         cudaFuncAttributeMaxDynamicSharedMemorySize, smem_bytes);
    sagpool_kernel<<<NG, NT, smem_bytes>>>(x, ei, W1, b1, W2, b2, W3, b3,
                                           Wa, ba, M1, c1, M2, c2, M3, c3, out);
}